// round 1
// baseline (speedup 1.0000x reference)
#include <cuda_runtime.h>
#include <math.h>

#define NN 30000
#define NE 480000
#define NG 300
#define NDIM 64
#define EDIM 41
#define FCW 128
#define NCONV 6
#define EPSV 1e-5f
#define EPB 256   // edges per block in pass A
#define ECH 8     // edge chunk staged in smem

// ---- scratch (static device globals; no runtime allocation) ----
__device__ float g_nf[NN * NDIM];     // node features (7.7 MB)
__device__ float g_P[NN * 256];       // [P1 | P2] per node (30.7 MB, L2-resident)
__device__ float g_z[NE * 128];       // pre-BN edge activations (245 MB)
__device__ float g_agg[NN * NDIM];    // segment-sum accumulator
__device__ float g_stats[256];        // sum[0:128], sumsq[128:256]
__device__ float g_sb[256];           // BN scale[0:128], bias[128:256]
__device__ float g_gsum[NG * NDIM];
__device__ float g_gcnt[NG];

__device__ __forceinline__ float sp_f(float x) {
    // softplus, stable
    return x > 20.f ? x : log1pf(__expf(x));
}
__device__ __forceinline__ float sig_f(float x) {
    return 1.f / (1.f + __expf(-x));
}

// ---------------- embed: nf = x @ embW + embB  (30000x92 @ 92x64) ----------------
__global__ void k_embed(const float* __restrict__ x,
                        const float* __restrict__ embW,
                        const float* __restrict__ embB) {
    int c = threadIdx.x;           // 0..63 output column
    float w[92];
#pragma unroll
    for (int k = 0; k < 92; k++) w[k] = embW[k * 64 + c];
    float b = embB[c];

    __shared__ float xs[8][92];
    int v0 = blockIdx.x * 8;
    for (int i = threadIdx.x; i < 8 * 92; i += 64) {
        int n = i / 92, k = i % 92;
        int v = v0 + n;
        xs[n][k] = (v < NN) ? x[v * 92 + k] : 0.f;
    }
    __syncthreads();
#pragma unroll 2
    for (int n = 0; n < 8; n++) {
        int v = v0 + n;
        if (v >= NN) break;
        float acc = b;
#pragma unroll
        for (int k = 0; k < 92; k++) acc += xs[n][k] * w[k];
        g_nf[v * 64 + c] = acc;
    }
}

// ---------------- per-layer zero of agg + stats ----------------
__global__ void k_zero_layer() {
    int i = blockIdx.x * blockDim.x + threadIdx.x;
    if (i < NN * NDIM) g_agg[i] = 0.f;
    if (i < 256) g_stats[i] = 0.f;
}

// ---------------- P = nf @ [W_dst | W_src]  (30000x64 @ 64x256) ----------------
__global__ void k_pgemm(const float* __restrict__ convW, int l) {
    int j = threadIdx.x;  // 0..255 output column
    const float* W = convW + l * 169 * 128;
    float w[64];
#pragma unroll
    for (int d = 0; d < 64; d++)
        w[d] = (j < 128) ? W[d * 128 + j] : W[(64 + d) * 128 + (j - 128)];

    __shared__ float nfs[16][64];
    int v0 = blockIdx.x * 16;
    for (int i = threadIdx.x; i < 16 * 64; i += 256) {
        int n = i / 64, d = i % 64;
        int v = v0 + n;
        nfs[n][d] = (v < NN) ? g_nf[v * 64 + d] : 0.f;
    }
    __syncthreads();
#pragma unroll 2
    for (int n = 0; n < 16; n++) {
        int v = v0 + n;
        if (v >= NN) break;
        float acc = 0.f;
#pragma unroll
        for (int d = 0; d < 64; d++) acc += nfs[n][d] * w[d];
        g_P[v * 256 + j] = acc;
    }
}

// ---------------- pass A: z = P1[dst] + P2[src] + ea@W3 + b ; stats ----------------
// blockDim 64; thread owns columns c0=t, c0+64 with W3 columns register-resident.
__global__ void k_passA(const float* __restrict__ edge_attr,
                        const int* __restrict__ eidx,
                        const float* __restrict__ convW,
                        const float* __restrict__ convB, int l) {
    int t = threadIdx.x;       // 0..63
    int c0 = t, c1 = t + 64;
    const float* W = convW + (l * 169 + 128) * 128;  // rows 128..168 = edge_attr part
    float w0[EDIM], w1[EDIM];
#pragma unroll
    for (int k = 0; k < EDIM; k++) {
        w0[k] = W[k * 128 + c0];
        w1[k] = W[k * 128 + c1];
    }
    float b0 = convB[l * 128 + c0];
    float b1 = convB[l * 128 + c1];

    __shared__ float eas[ECH][EDIM];
    __shared__ int ssrc[ECH], sdst[ECH];

    float sum0 = 0.f, sq0 = 0.f, sum1 = 0.f, sq1 = 0.f;

    int e0 = blockIdx.x * EPB;
    int eend = min(e0 + EPB, NE);
    for (int eb = e0; eb < eend; eb += ECH) {
        int ncur = min(ECH, eend - eb);
        __syncthreads();
        for (int i = t; i < ncur * EDIM; i += 64) {
            int e = i / EDIM, k = i % EDIM;
            eas[e][k] = edge_attr[(eb + e) * EDIM + k];
        }
        if (t < ncur) {
            ssrc[t] = eidx[eb + t];        // edge_index[0] = src
            sdst[t] = eidx[NE + eb + t];   // edge_index[1] = dst
        }
        __syncthreads();
        for (int e = 0; e < ncur; e++) {
            float a0 = b0, a1 = b1;
#pragma unroll
            for (int k = 0; k < EDIM; k++) {
                float a = eas[e][k];
                a0 += a * w0[k];
                a1 += a * w1[k];
            }
            int s = ssrc[e], d = sdst[e];
            float z0 = a0 + g_P[d * 256 + c0] + g_P[s * 256 + 128 + c0];
            float z1 = a1 + g_P[d * 256 + c1] + g_P[s * 256 + 128 + c1];
            int eg = eb + e;
            g_z[eg * 128 + c0] = z0;
            g_z[eg * 128 + c1] = z1;
            sum0 += z0; sq0 += z0 * z0;
            sum1 += z1; sq1 += z1 * z1;
        }
    }
    atomicAdd(&g_stats[c0], sum0);
    atomicAdd(&g_stats[c1], sum1);
    atomicAdd(&g_stats[128 + c0], sq0);
    atomicAdd(&g_stats[128 + c1], sq1);
}

// ---------------- finalize BN stats -> scale/bias ----------------
__global__ void k_stats(const float* __restrict__ bnG,
                        const float* __restrict__ bnB, int l) {
    int c = threadIdx.x;  // 0..127
    float inv = 1.f / (float)NE;
    float mu = g_stats[c] * inv;
    float var = g_stats[128 + c] * inv - mu * mu;
    float sc = rsqrtf(var + EPSV) * bnG[l * 128 + c];
    g_sb[c] = sc;
    g_sb[128 + c] = bnB[l * 128 + c] - mu * sc;
}

// ---------------- pass B: BN apply + gate + scatter-add ----------------
__global__ void k_passB(const int* __restrict__ eidx) {
    int tid = blockIdx.x * blockDim.x + threadIdx.x;
    int e = tid >> 6;
    int c = tid & 63;
    if (e >= NE) return;
    int d = eidx[NE + e];
    float z1 = g_z[e * 128 + c] * g_sb[c] + g_sb[128 + c];
    float z2 = g_z[e * 128 + 64 + c] * g_sb[64 + c] + g_sb[192 + c];
    float m = sig_f(z1) * sp_f(z2);
    atomicAdd(&g_agg[d * 64 + c], m);
}

// ---------------- node update: softplus(LN(agg) + nf) ----------------
__global__ void k_node(const float* __restrict__ lnG,
                       const float* __restrict__ lnB, int l) {
    int v = blockIdx.x * 4 + (threadIdx.x >> 5);
    int lane = threadIdx.x & 31;
    if (v >= NN) return;
    float a0 = g_agg[v * 64 + lane];
    float a1 = g_agg[v * 64 + 32 + lane];
    float s = a0 + a1;
    float sq = a0 * a0 + a1 * a1;
#pragma unroll
    for (int o = 16; o > 0; o >>= 1) {
        s  += __shfl_xor_sync(0xffffffff, s, o);
        sq += __shfl_xor_sync(0xffffffff, sq, o);
    }
    float mu = s * (1.f / 64.f);
    float var = sq * (1.f / 64.f) - mu * mu;
    float rs = rsqrtf(var + EPSV);
    float l0 = (a0 - mu) * rs * lnG[l * 64 + lane] + lnB[l * 64 + lane];
    float l1 = (a1 - mu) * rs * lnG[l * 64 + 32 + lane] + lnB[l * 64 + 32 + lane];
    g_nf[v * 64 + lane]      = sp_f(l0 + g_nf[v * 64 + lane]);
    g_nf[v * 64 + 32 + lane] = sp_f(l1 + g_nf[v * 64 + 32 + lane]);
}

// ---------------- pooling ----------------
__global__ void k_zero_pool() {
    int i = blockIdx.x * blockDim.x + threadIdx.x;
    if (i < NG * NDIM) g_gsum[i] = 0.f;
    if (i < NG) g_gcnt[i] = 0.f;
}

__global__ void k_pool(const int* __restrict__ batch) {
    int tid = blockIdx.x * blockDim.x + threadIdx.x;
    int v = tid >> 6;
    int c = tid & 63;
    if (v >= NN) return;
    int g = batch[v];
    atomicAdd(&g_gsum[g * 64 + c], g_nf[v * 64 + c]);
    if (c == 0) atomicAdd(&g_gcnt[g], 1.f);
}

// ---------------- final MLP head (300 graphs) ----------------
__global__ void k_mlp(const float* __restrict__ fc1W, const float* __restrict__ fc1B,
                      const float* __restrict__ fcsW, const float* __restrict__ fcsB,
                      const float* __restrict__ foW, const float* __restrict__ foB,
                      float* __restrict__ out) {
    int g = blockIdx.x;
    int c = threadIdx.x;  // 0..127
    __shared__ float s[64];
    __shared__ float h[128];
    __shared__ float red[128];

    if (c < 64) {
        float cnt = g_gcnt[g];
        s[c] = g_gsum[g * 64 + c] / fmaxf(cnt, 1.f);
    }
    __syncthreads();
    float acc = fc1B[c];
#pragma unroll 4
    for (int k = 0; k < 64; k++) acc += s[k] * fc1W[k * 128 + c];
    h[c] = sp_f(acc);
    __syncthreads();
    for (int lh = 0; lh < 3; lh++) {
        float a = fcsB[lh * 128 + c];
#pragma unroll 4
        for (int k = 0; k < 128; k++) a += h[k] * fcsW[(lh * 128 + k) * 128 + c];
        __syncthreads();
        h[c] = sp_f(a);
        __syncthreads();
    }
    red[c] = h[c] * foW[c];
    __syncthreads();
#pragma unroll
    for (int o = 64; o > 0; o >>= 1) {
        if (c < o) red[c] += red[c + o];
        __syncthreads();
    }
    if (c == 0) out[g] = red[0] + foB[0];
}

// ---------------- launch ----------------
extern "C" void kernel_launch(void* const* d_in, const int* in_sizes, int n_in,
                              void* d_out, int out_size) {
    const float* x        = (const float*)d_in[0];
    const float* edge_attr= (const float*)d_in[1];
    const float* embW     = (const float*)d_in[2];
    const float* embB     = (const float*)d_in[3];
    const float* convW    = (const float*)d_in[4];
    const float* convB    = (const float*)d_in[5];
    const float* bnG      = (const float*)d_in[6];
    const float* bnB      = (const float*)d_in[7];
    const float* lnG      = (const float*)d_in[8];
    const float* lnB      = (const float*)d_in[9];
    const float* fc1W     = (const float*)d_in[10];
    const float* fc1B     = (const float*)d_in[11];
    const float* fcsW     = (const float*)d_in[12];
    const float* fcsB     = (const float*)d_in[13];
    const float* foW      = (const float*)d_in[14];
    const float* foB      = (const float*)d_in[15];
    const int*   eidx     = (const int*)d_in[16];
    const int*   batch    = (const int*)d_in[17];
    float* out = (float*)d_out;

    k_embed<<<(NN + 7) / 8, 64>>>(x, embW, embB);

    for (int l = 0; l < NCONV; l++) {
        k_zero_layer<<<(NN * NDIM + 255) / 256, 256>>>();
        k_pgemm<<<(NN + 15) / 16, 256>>>(convW, l);
        k_passA<<<(NE + EPB - 1) / EPB, 64>>>(edge_attr, eidx, convW, convB, l);
        k_stats<<<1, 128>>>(bnG, bnB, l);
        k_passB<<<(NE * 64 + 255) / 256, 256>>>(eidx);
        k_node<<<(NN + 3) / 4, 128>>>(lnG, lnB, l);
    }

    k_zero_pool<<<(NG * NDIM + 255) / 256, 256>>>();
    k_pool<<<(NN * 64 + 255) / 256, 256>>>(batch);
    k_mlp<<<NG, 128>>>(fc1W, fc1B, fcsW, fcsB, foW, foB, out);
}

// round 4
// speedup vs baseline: 1.3388x; 1.3388x over previous
#include <cuda_runtime.h>
#include <cuda_fp16.h>
#include <cuda_bf16.h>
#include <stdint.h>
#include <math.h>

#define NN 30000
#define NE 480000
#define NG 300
#define NDIM 64
#define EDIM 41
#define NCONV 6
#define EPSV 1e-5f
#define KPAD 48

// ---- scratch (static device globals; no runtime allocation) ----
__device__ float g_nf[NN * NDIM];            // node features (7.7 MB)
__device__ float g_P[NN * 256];              // [P1 | P2] per node (30.7 MB, L2-resident)
__device__ __half g_EWL[(size_t)NE * 128];   // per-layer edge GEMM result (123 MB)
__device__ __nv_bfloat16 g_w3hi[NCONV * 128 * KPAD];
__device__ __nv_bfloat16 g_w3lo[NCONV * 128 * KPAD];
__device__ float g_agg[NN * NDIM];
__device__ float g_stats[256];               // sum[0:128], sumsq[128:256]
__device__ float g_sb[256];                  // BN scale[0:128], bias[128:256]
__device__ float g_gsum[NG * NDIM];
__device__ float g_gcnt[NG];

__device__ __forceinline__ float sp_f(float x) {
    return x > 20.f ? x : log1pf(__expf(x));
}
__device__ __forceinline__ float sig_f(float x) {
    return 1.f / (1.f + __expf(-x));
}

#define MMA_BF16(c0,c1,c2,c3,a0,a1,a2,a3,b0,b1) \
  asm volatile("mma.sync.aligned.m16n8k16.row.col.f32.bf16.bf16.f32 " \
      "{%0,%1,%2,%3}, {%4,%5,%6,%7}, {%8,%9}, {%0,%1,%2,%3};" \
      : "+f"(c0),"+f"(c1),"+f"(c2),"+f"(c3) \
      : "r"(a0),"r"(a1),"r"(a2),"r"(a3),"r"(b0),"r"(b1))

// ---------------- embed: nf = x @ embW + embB ----------------
__global__ void k_embed(const float* __restrict__ x,
                        const float* __restrict__ embW,
                        const float* __restrict__ embB) {
    int c = threadIdx.x;           // 0..63
    float w[92];
#pragma unroll
    for (int k = 0; k < 92; k++) w[k] = embW[k * 64 + c];
    float b = embB[c];

    __shared__ float xs[8][92];
    int v0 = blockIdx.x * 8;
    for (int i = threadIdx.x; i < 8 * 92; i += 64) {
        int n = i / 92, k = i % 92;
        int v = v0 + n;
        xs[n][k] = (v < NN) ? x[v * 92 + k] : 0.f;
    }
    __syncthreads();
#pragma unroll 2
    for (int n = 0; n < 8; n++) {
        int v = v0 + n;
        if (v >= NN) break;
        float acc = b;
#pragma unroll
        for (int k = 0; k < 92; k++) acc += xs[n][k] * w[k];
        g_nf[v * 64 + c] = acc;
    }
}

// ---------------- prep: W3 (rows 128..168 of conv weights) -> bf16 hi/lo, [l][c][k] ----------------
__global__ void k_prepw(const float* __restrict__ convW) {
    int i = blockIdx.x * 256 + threadIdx.x;  // over 6*128*48
    if (i >= NCONV * 128 * KPAD) return;
    int n = i / KPAD, k = i - n * KPAD;
    int l = n >> 7, c = n & 127;
    float v = (k < EDIM) ? convW[(l * 169 + 128 + k) * 128 + c] : 0.f;
    __nv_bfloat16 h = __float2bfloat16(v);
    g_w3hi[i] = h;
    g_w3lo[i] = __float2bfloat16(v - __bfloat162float(h));
}

// ---------------- EWL = ea @ W3_l  (480000x41 @ 41x128) via bf16-split mma ----------------
// grid 3750 m-tiles, block 256 (8 warps). Block tile M128 x N128, K=48.
__global__ void k_ewgemm(const float* __restrict__ ea, int l) {
    __shared__ __nv_bfloat16 Ahi[128 * KPAD], Alo[128 * KPAD];
    __shared__ __nv_bfloat16 Bhi[128 * KPAD], Blo[128 * KPAD];
    int tid = threadIdx.x;
    int m0 = blockIdx.x * 128;

    for (int idx = tid; idx < 128 * KPAD; idx += 256) {
        int r = idx / KPAD, k = idx - r * KPAD;
        float v = (k < EDIM) ? ea[(size_t)(m0 + r) * EDIM + k] : 0.f;
        __nv_bfloat16 h = __float2bfloat16(v);
        Ahi[idx] = h;
        Alo[idx] = __float2bfloat16(v - __bfloat162float(h));
    }
    const __nv_bfloat16* w3h = g_w3hi + l * 128 * KPAD;
    const __nv_bfloat16* w3l = g_w3lo + l * 128 * KPAD;
    for (int idx = tid; idx < 128 * KPAD; idx += 256) {
        Bhi[idx] = w3h[idx];
        Blo[idx] = w3l[idx];
    }
    __syncthreads();

    int w = tid >> 5, lane = tid & 31;
    int g = lane >> 2, tq = lane & 3;
    float acc[64];
#pragma unroll
    for (int i = 0; i < 64; i++) acc[i] = 0.f;
    int ar0 = w * 16 + g;

#pragma unroll
    for (int ks = 0; ks < 3; ks++) {
        int kb = ks * 16 + tq * 2;
        uint32_t ah0 = *(const uint32_t*)&Ahi[ar0 * KPAD + kb];
        uint32_t ah1 = *(const uint32_t*)&Ahi[(ar0 + 8) * KPAD + kb];
        uint32_t ah2 = *(const uint32_t*)&Ahi[ar0 * KPAD + kb + 8];
        uint32_t ah3 = *(const uint32_t*)&Ahi[(ar0 + 8) * KPAD + kb + 8];
        uint32_t al0 = *(const uint32_t*)&Alo[ar0 * KPAD + kb];
        uint32_t al1 = *(const uint32_t*)&Alo[(ar0 + 8) * KPAD + kb];
        uint32_t al2 = *(const uint32_t*)&Alo[ar0 * KPAD + kb + 8];
        uint32_t al3 = *(const uint32_t*)&Alo[(ar0 + 8) * KPAD + kb + 8];
#pragma unroll
        for (int ns = 0; ns < 16; ns++) {
            int bn = ns * 8 + g;
            uint32_t bh0 = *(const uint32_t*)&Bhi[bn * KPAD + kb];
            uint32_t bh1 = *(const uint32_t*)&Bhi[bn * KPAD + kb + 8];
            uint32_t bl0 = *(const uint32_t*)&Blo[bn * KPAD + kb];
            uint32_t bl1 = *(const uint32_t*)&Blo[bn * KPAD + kb + 8];
            float* c = acc + ns * 4;
            MMA_BF16(c[0], c[1], c[2], c[3], ah0, ah1, ah2, ah3, bh0, bh1);
            MMA_BF16(c[0], c[1], c[2], c[3], ah0, ah1, ah2, ah3, bl0, bl1);
            MMA_BF16(c[0], c[1], c[2], c[3], al0, al1, al2, al3, bh0, bh1);
        }
    }

    size_t row0 = m0 + w * 16 + g;
#pragma unroll
    for (int ns = 0; ns < 16; ns++) {
        int col = ns * 8 + tq * 2;
        ((__half2*)g_EWL)[(row0 * 128 + col) >> 1] =
            __floats2half2_rn(acc[ns * 4 + 0], acc[ns * 4 + 1]);
        ((__half2*)g_EWL)[((row0 + 8) * 128 + col) >> 1] =
            __floats2half2_rn(acc[ns * 4 + 2], acc[ns * 4 + 3]);
    }
}

// ---------------- per-layer zero of agg + stats ----------------
__global__ void k_zero_layer() {
    int i = blockIdx.x * blockDim.x + threadIdx.x;
    if (i < NN * NDIM) g_agg[i] = 0.f;
    if (i < 256) g_stats[i] = 0.f;
}

// ---------------- P = nf @ [W_dst | W_src]  (30000x64 @ 64x256) ----------------
__global__ void k_pgemm(const float* __restrict__ convW, int l) {
    int j = threadIdx.x;  // 0..255
    const float* W = convW + l * 169 * 128;
    float w[64];
#pragma unroll
    for (int d = 0; d < 64; d++)
        w[d] = (j < 128) ? W[d * 128 + j] : W[(64 + d) * 128 + (j - 128)];

    __shared__ float nfs[16][64];
    int v0 = blockIdx.x * 16;
    for (int i = threadIdx.x; i < 16 * 64; i += 256) {
        int n = i / 64, d = i % 64;
        int v = v0 + n;
        nfs[n][d] = (v < NN) ? g_nf[v * 64 + d] : 0.f;
    }
    __syncthreads();
#pragma unroll 2
    for (int n = 0; n < 16; n++) {
        int v = v0 + n;
        if (v >= NN) break;
        float acc = 0.f;
#pragma unroll
        for (int d = 0; d < 64; d++) acc += nfs[n][d] * w[d];
        g_P[v * 256 + j] = acc;
    }
}

// ---------------- pass A: BN statistics only (z recomputed, never stored) ----------------
// Conv bias cancels in BatchNorm (constant shift drops out of z - mu).
__global__ void k_statsA(const int* __restrict__ eidx) {
    int tid = threadIdx.x;
    int c = tid & 127, sub = tid >> 7;
    int e0 = blockIdx.x * 256;
    float s = 0.f, sq = 0.f;
#pragma unroll 4
    for (int i = 0; i < 128; i++) {
        int e = e0 + 2 * i + sub;
        int d = eidx[NE + e], sv = eidx[e];
        float z = __half2float(g_EWL[(size_t)e * 128 + c])
                + g_P[d * 256 + c] + g_P[sv * 256 + 128 + c];
        s += z; sq += z * z;
    }
    atomicAdd(&g_stats[c], s);
    atomicAdd(&g_stats[128 + c], sq);
}

// ---------------- finalize BN stats -> scale/bias ----------------
__global__ void k_stats(const float* __restrict__ bnG,
                        const float* __restrict__ bnB, int l) {
    int c = threadIdx.x;  // 0..127
    float inv = 1.f / (float)NE;
    float mu = g_stats[c] * inv;
    float var = g_stats[128 + c] * inv - mu * mu;
    float sc = rsqrtf(var + EPSV) * bnG[l * 128 + c];
    g_sb[c] = sc;
    g_sb[128 + c] = bnB[l * 128 + c] - mu * sc;
}

// ---------------- pass B: recompute z, BN apply + gate + scatter-add ----------------
__global__ void k_apply(const int* __restrict__ eidx) {
    __shared__ float sb[256];
    int tid = threadIdx.x;
    sb[tid] = g_sb[tid];
    __syncthreads();
    int cb = tid & 63, es = tid >> 6;
    int e0 = blockIdx.x * 256;
    float sc1 = sb[cb],      bi1 = sb[128 + cb];
    float sc2 = sb[64 + cb], bi2 = sb[192 + cb];
#pragma unroll 2
    for (int i = 0; i < 64; i++) {
        int e = e0 + 4 * i + es;
        int d = eidx[NE + e], sv = eidx[e];
        float z1 = __half2float(g_EWL[(size_t)e * 128 + cb])
                 + g_P[d * 256 + cb] + g_P[sv * 256 + 128 + cb];
        float z2 = __half2float(g_EWL[(size_t)e * 128 + 64 + cb])
                 + g_P[d * 256 + 64 + cb] + g_P[sv * 256 + 192 + cb];
        z1 = z1 * sc1 + bi1;
        z2 = z2 * sc2 + bi2;
        float m = sig_f(z1) * sp_f(z2);
        atomicAdd(&g_agg[d * 64 + cb], m);
    }
}

// ---------------- node update: softplus(LN(agg) + nf) ----------------
__global__ void k_node(const float* __restrict__ lnG,
                       const float* __restrict__ lnB, int l) {
    int v = blockIdx.x * 4 + (threadIdx.x >> 5);
    int lane = threadIdx.x & 31;
    if (v >= NN) return;
    float a0 = g_agg[v * 64 + lane];
    float a1 = g_agg[v * 64 + 32 + lane];
    float s = a0 + a1;
    float sq = a0 * a0 + a1 * a1;
#pragma unroll
    for (int o = 16; o > 0; o >>= 1) {
        s  += __shfl_xor_sync(0xffffffff, s, o);
        sq += __shfl_xor_sync(0xffffffff, sq, o);
    }
    float mu = s * (1.f / 64.f);
    float var = sq * (1.f / 64.f) - mu * mu;
    float rs = rsqrtf(var + EPSV);
    float l0 = (a0 - mu) * rs * lnG[l * 64 + lane] + lnB[l * 64 + lane];
    float l1 = (a1 - mu) * rs * lnG[l * 64 + 32 + lane] + lnB[l * 64 + 32 + lane];
    g_nf[v * 64 + lane]      = sp_f(l0 + g_nf[v * 64 + lane]);
    g_nf[v * 64 + 32 + lane] = sp_f(l1 + g_nf[v * 64 + 32 + lane]);
}

// ---------------- pooling ----------------
__global__ void k_zero_pool() {
    int i = blockIdx.x * blockDim.x + threadIdx.x;
    if (i < NG * NDIM) g_gsum[i] = 0.f;
    if (i < NG) g_gcnt[i] = 0.f;
}

__global__ void k_pool(const int* __restrict__ batch) {
    int tid = blockIdx.x * blockDim.x + threadIdx.x;
    int v = tid >> 6;
    int c = tid & 63;
    if (v >= NN) return;
    int g = batch[v];
    atomicAdd(&g_gsum[g * 64 + c], g_nf[v * 64 + c]);
    if (c == 0) atomicAdd(&g_gcnt[g], 1.f);
}

// ---------------- final MLP head (300 graphs) ----------------
__global__ void k_mlp(const float* __restrict__ fc1W, const float* __restrict__ fc1B,
                      const float* __restrict__ fcsW, const float* __restrict__ fcsB,
                      const float* __restrict__ foW, const float* __restrict__ foB,
                      float* __restrict__ out) {
    int g = blockIdx.x;
    int c = threadIdx.x;  // 0..127
    __shared__ float s[64];
    __shared__ float h[128];
    __shared__ float red[128];

    if (c < 64) {
        float cnt = g_gcnt[g];
        s[c] = g_gsum[g * 64 + c] / fmaxf(cnt, 1.f);
    }
    __syncthreads();
    float acc = fc1B[c];
#pragma unroll 4
    for (int k = 0; k < 64; k++) acc += s[k] * fc1W[k * 128 + c];
    h[c] = sp_f(acc);
    __syncthreads();
    for (int lh = 0; lh < 3; lh++) {
        float a = fcsB[lh * 128 + c];
#pragma unroll 4
        for (int k = 0; k < 128; k++) a += h[k] * fcsW[(lh * 128 + k) * 128 + c];
        __syncthreads();
        h[c] = sp_f(a);
        __syncthreads();
    }
    red[c] = h[c] * foW[c];
    __syncthreads();
#pragma unroll
    for (int o = 64; o > 0; o >>= 1) {
        if (c < o) red[c] += red[c + o];
        __syncthreads();
    }
    if (c == 0) out[g] = red[0] + foB[0];
}

// ---------------- launch ----------------
extern "C" void kernel_launch(void* const* d_in, const int* in_sizes, int n_in,
                              void* d_out, int out_size) {
    const float* x        = (const float*)d_in[0];
    const float* edge_attr= (const float*)d_in[1];
    const float* embW     = (const float*)d_in[2];
    const float* embB     = (const float*)d_in[3];
    const float* convW    = (const float*)d_in[4];
    const float* bnG      = (const float*)d_in[6];
    const float* bnB      = (const float*)d_in[7];
    const float* lnG      = (const float*)d_in[8];
    const float* lnB      = (const float*)d_in[9];
    const float* fc1W     = (const float*)d_in[10];
    const float* fc1B     = (const float*)d_in[11];
    const float* fcsW     = (const float*)d_in[12];
    const float* fcsB     = (const float*)d_in[13];
    const float* foW      = (const float*)d_in[14];
    const float* foB      = (const float*)d_in[15];
    const int*   eidx     = (const int*)d_in[16];
    const int*   batch    = (const int*)d_in[17];
    float* out = (float*)d_out;

    k_embed<<<(NN + 7) / 8, 64>>>(x, embW, embB);
    k_prepw<<<(NCONV * 128 * KPAD + 255) / 256, 256>>>(convW);

    for (int l = 0; l < NCONV; l++) {
        k_zero_layer<<<(NN * NDIM + 255) / 256, 256>>>();
        k_ewgemm<<<NE / 128, 256>>>(edge_attr, l);
        k_pgemm<<<(NN + 15) / 16, 256>>>(convW, l);
        k_statsA<<<NE / 256, 256>>>(eidx);
        k_stats<<<1, 128>>>(bnG, bnB, l);
        k_apply<<<NE / 256, 256>>>(eidx);
        k_node<<<(NN + 3) / 4, 128>>>(lnG, lnB, l);
    }

    k_zero_pool<<<(NG * NDIM + 255) / 256, 256>>>();
    k_pool<<<(NN * 64 + 255) / 256, 256>>>(batch);
    k_mlp<<<NG, 128>>>(fc1W, fc1B, fcsW, fcsB, foW, foB, out);
}